// round 9
// baseline (speedup 1.0000x reference)
#include <cuda_runtime.h>

#define BB 4
#define NN 8192
#define CC 64
#define OUTD 64
#define KNNK 36
#define BN (BB*NN)
#define KBLK 128
#define NSPLIT 4
#define QPART (NN/NSPLIT)      // 2048 candidates per split
#define TILE 256
#define SAMPLE 512             // phase-A sample size
#define PKEEP 32               // phase-A top-K (threshold = 32nd smallest)
#define CAP 192                // survivor capacity per thread

// Device scratch (allocation-free rule: __device__ globals)
__device__ float4 g_xyz4[BN];             // (sq, x, y, z) packed per point
__device__ float  g_vfeat[BN*OUTD];       // relu([feature,xyz] @ W_v + b_v)
__device__ float  g_pd[NSPLIT*BN*KNNK];   // partial top-36 distances
__device__ int    g_pi[NSPLIT*BN*KNNK];   // partial top-36 indices
__device__ unsigned char g_fail[NSPLIT*BN]; // per (q,quarter) fallback flag

// ---------------------------------------------------------------------------
__global__ void pack_xyz_kernel(const float* __restrict__ xyz) {
    int i = blockIdx.x * blockDim.x + threadIdx.x;
    if (i >= BN) return;
    float x = xyz[3*i], y = xyz[3*i+1], z = xyz[3*i+2];
    g_xyz4[i] = make_float4(x*x + y*y + z*z, x, y, z);
}

// ---------------------------------------------------------------------------
// v_feat = relu(concat([feature, xyz]) @ W_v + b_v)   (B,N,64)
// ---------------------------------------------------------------------------
__global__ __launch_bounds__(256) void vfeat_kernel(
    const float* __restrict__ feature,
    const float* __restrict__ xyz,
    const float* __restrict__ Wv,
    const float* __restrict__ bv)
{
    __shared__ float fsh[4][68];
    int sub = threadIdx.x >> 6;
    int t   = threadIdx.x & 63;
    int p   = blockIdx.x * 4 + sub;
    fsh[sub][t] = feature[p*64 + t];
    if (t < 3) fsh[sub][64 + t] = xyz[p*3 + t];
    __syncthreads();
    const float* f = fsh[sub];
    float acc = bv[t];
    #pragma unroll
    for (int c = 0; c < 67; c++)
        acc = fmaf(f[c], Wv[c*64 + t], acc);
    g_vfeat[p*64 + t] = fmaxf(acc, 0.0f);
}

// ---------------------------------------------------------------------------
// Equality-replace insert into a 36-entry register list.
// ---------------------------------------------------------------------------
__device__ __forceinline__ void topk_insert_eq(
    float d, int idx, float* kd, int* ki, float& worst)
{
    #pragma unroll
    for (int s = 0; s < KNNK; s++) {
        bool h = (kd[s] == worst);
        kd[s] = h ? d   : kd[s];
        ki[s] = h ? idx : ki[s];
    }
    float w = kd[0];
    #pragma unroll
    for (int s = 1; s < KNNK; s++)
        w = fmaxf(w, kd[s]);
    worst = w;
}

// ---------------------------------------------------------------------------
// KNN via threshold + collect over a quarter (blockIdx.y = quarter).
// Phase A: top-32 distances of first SAMPLE candidates (direct fill of the
//          first 32, then bitmask-gated inserts) -> threshold T.
// Phase B: collect candidates with d <= T (fixed threshold, chain-free
//          bitmask scan) into per-thread local survivor arrays.
// Phase C: exact top-36 among survivors; out-of-range cnt -> fallback flag.
// ---------------------------------------------------------------------------
__global__ __launch_bounds__(KBLK) void knn_select_kernel() {
    __shared__ float4 tile[TILE];
    const unsigned FULL = 0xffffffffu;

    int tid = threadIdx.x;
    int q = blockIdx.x * KBLK + tid;
    int h = blockIdx.y;
    int b = q >> 13;

    float4 me = g_xyz4[q];
    float nx = -2.0f * me.y, ny = -2.0f * me.z, nz = -2.0f * me.w;

    const float4* __restrict__ cand = g_xyz4 + b * NN + h * QPART;
    const int idx_off = h * QPART;

    // ---------------- Phase A: threshold = 32nd smallest of first 512 -------
    float pd[PKEEP];
    float worstA;
    for (int base = 0; base < SAMPLE; base += TILE) {
        __syncthreads();
        tile[tid]        = cand[base + tid];
        tile[tid + KBLK] = cand[base + tid + KBLK];
        __syncthreads();

        int js_start = 0;
        if (base == 0) {
            #pragma unroll
            for (int s = 0; s < PKEEP; s++) {
                float4 c = tile[s];
                float d = fmaf(nx, c.y, c.x);
                d = fmaf(ny, c.z, d); d = fmaf(nz, c.w, d);
                pd[s] = d;
            }
            float w = pd[0];
            #pragma unroll
            for (int s = 1; s < PKEEP; s++) w = fmaxf(w, pd[s]);
            worstA = w;
            js_start = PKEEP;     // first 32 consumed by the fill
        }

        for (int js = js_start; js < TILE; js += 32) {
            unsigned m0 = 0, m1 = 0;
            #pragma unroll
            for (int jj = 0; jj < 16; jj++) {
                float4 c = tile[js + jj];
                float d = fmaf(nx, c.y, c.x);
                d = fmaf(ny, c.z, d); d = fmaf(nz, c.w, d);
                m0 |= (d < worstA) ? (1u << jj) : 0u;
            }
            #pragma unroll
            for (int jj = 16; jj < 32; jj++) {
                float4 c = tile[js + jj];
                float d = fmaf(nx, c.y, c.x);
                d = fmaf(ny, c.z, d); d = fmaf(nz, c.w, d);
                m1 |= (d < worstA) ? (1u << jj) : 0u;
            }
            unsigned mask = m0 | m1;
            if (__any_sync(FULL, mask != 0u)) {
                while (mask) {
                    int jj = __ffs(mask) - 1;
                    mask &= mask - 1;
                    float4 c = tile[js + jj];
                    float d = fmaf(nx, c.y, c.x);
                    d = fmaf(ny, c.z, d); d = fmaf(nz, c.w, d);
                    if (d < worstA) {
                        #pragma unroll
                        for (int s = 0; s < PKEEP; s++) {
                            bool hh = (pd[s] == worstA);
                            pd[s] = hh ? d : pd[s];
                        }
                        float w = pd[0];
                        #pragma unroll
                        for (int s = 1; s < PKEEP; s++) w = fmaxf(w, pd[s]);
                        worstA = w;
                    }
                }
            }
        }
    }
    const float T = worstA;   // fixed threshold for phase B

    // ---------------- Phase B: collect survivors (d <= T) -------------------
    float sd[CAP];
    int   si[CAP];
    int cnt = 0;

    for (int base = 0; base < QPART; base += TILE) {
        __syncthreads();
        tile[tid]        = cand[base + tid];
        tile[tid + KBLK] = cand[base + tid + KBLK];
        __syncthreads();

        for (int js = 0; js < TILE; js += 32) {
            unsigned m0 = 0, m1 = 0, m2 = 0, m3 = 0;
            #pragma unroll
            for (int jj = 0; jj < 8; jj++) {
                float4 c = tile[js + jj];
                float d = fmaf(nx, c.y, c.x);
                d = fmaf(ny, c.z, d); d = fmaf(nz, c.w, d);
                m0 |= (d <= T) ? (1u << jj) : 0u;
            }
            #pragma unroll
            for (int jj = 8; jj < 16; jj++) {
                float4 c = tile[js + jj];
                float d = fmaf(nx, c.y, c.x);
                d = fmaf(ny, c.z, d); d = fmaf(nz, c.w, d);
                m1 |= (d <= T) ? (1u << jj) : 0u;
            }
            #pragma unroll
            for (int jj = 16; jj < 24; jj++) {
                float4 c = tile[js + jj];
                float d = fmaf(nx, c.y, c.x);
                d = fmaf(ny, c.z, d); d = fmaf(nz, c.w, d);
                m2 |= (d <= T) ? (1u << jj) : 0u;
            }
            #pragma unroll
            for (int jj = 24; jj < 32; jj++) {
                float4 c = tile[js + jj];
                float d = fmaf(nx, c.y, c.x);
                d = fmaf(ny, c.z, d); d = fmaf(nz, c.w, d);
                m3 |= (d <= T) ? (1u << jj) : 0u;
            }
            unsigned mask = (m0 | m1) | (m2 | m3);
            if (__any_sync(FULL, mask != 0u)) {
                while (mask) {
                    int jj = __ffs(mask) - 1;
                    mask &= mask - 1;
                    float4 c = tile[js + jj];
                    float d = fmaf(nx, c.y, c.x);
                    d = fmaf(ny, c.z, d); d = fmaf(nz, c.w, d);
                    if (cnt < CAP) { sd[cnt] = d; si[cnt] = idx_off + base + js + jj; }
                    cnt++;
                }
            }
        }
    }

    // ---------------- Phase C: exact top-36 among survivors -----------------
    bool fail = (cnt < KNNK) || (cnt > CAP);
    g_fail[(size_t)h * BN + q] = fail ? 1 : 0;

    if (!fail) {
        float kd[KNNK];
        int   ki[KNNK];
        #pragma unroll
        for (int s = 0; s < KNNK; s++) { kd[s] = sd[s]; ki[s] = si[s]; }
        float worst = kd[0];
        #pragma unroll
        for (int s = 1; s < KNNK; s++) worst = fmaxf(worst, kd[s]);

        for (int it = KNNK; it < cnt; it++) {
            float d = sd[it];
            if (d < worst)
                topk_insert_eq(d, si[it], kd, ki, worst);
        }

        size_t o = ((size_t)h * BN + q) * KNNK;
        #pragma unroll
        for (int s = 0; s < KNNK; s++) {
            g_pd[o + s] = kd[s];
            g_pi[o + s] = ki[s];
        }
    }
}

// ---------------------------------------------------------------------------
// Fallback: exact streaming top-36 for flagged (q,quarter) pairs (~0 expected).
// ---------------------------------------------------------------------------
__global__ __launch_bounds__(KBLK) void knn_fallback_kernel() {
    int tid = threadIdx.x;
    int q = blockIdx.x * KBLK + tid;
    int h = blockIdx.y;
    if (!g_fail[(size_t)h * BN + q]) return;

    int b = q >> 13;
    float4 me = g_xyz4[q];
    float nx = -2.0f * me.y, ny = -2.0f * me.z, nz = -2.0f * me.w;
    const float4* __restrict__ cand = g_xyz4 + b * NN + h * QPART;
    const int idx_off = h * QPART;

    float kd[KNNK];
    int   ki[KNNK];
    #pragma unroll
    for (int s = 0; s < KNNK; s++) {
        float4 c = __ldg(cand + s);
        float d = fmaf(nx, c.y, c.x);
        d = fmaf(ny, c.z, d); d = fmaf(nz, c.w, d);
        kd[s] = d; ki[s] = idx_off + s;
    }
    float worst = kd[0];
    #pragma unroll
    for (int s = 1; s < KNNK; s++) worst = fmaxf(worst, kd[s]);

    for (int j = KNNK; j < QPART; j++) {
        float4 c = __ldg(cand + j);
        float d = fmaf(nx, c.y, c.x);
        d = fmaf(ny, c.z, d); d = fmaf(nz, c.w, d);
        if (d < worst)
            topk_insert_eq(d, idx_off + j, kd, ki, worst);
    }

    size_t o = ((size_t)h * BN + q) * KNNK;
    #pragma unroll
    for (int s = 0; s < KNNK; s++) {
        g_pd[o + s] = kd[s];
        g_pi[o + s] = ki[s];
    }
}

// ---------------------------------------------------------------------------
// Order-preserving float -> uint map for bit-bisection selection.
// ---------------------------------------------------------------------------
__device__ __forceinline__ unsigned f2mono(float f) {
    unsigned u = __float_as_uint(f);
    return (u & 0x80000000u) ? ~u : (u | 0x80000000u);
}

// ---------------------------------------------------------------------------
// Fused 4-way merge + attention + suffix GEMM. Warp per point.
// Merge: exact top-36 of 144 (=4x36) partials via warp ballot bit-bisection
// (36th-smallest value V over all 4 lists), then ballot-prefix compaction.
// ---------------------------------------------------------------------------
__global__ __launch_bounds__(256) void attn_kernel(
    const float* __restrict__ feature,
    const float* __restrict__ Wsuf,
    const float* __restrict__ bsuf,
    float* __restrict__ out)
{
    __shared__ int   ish[8][40];
    __shared__ float osh[8][64];
    const unsigned FULL = 0xffffffffu;
    int w    = threadIdx.x >> 5;
    int lane = threadIdx.x & 31;
    int p    = blockIdx.x * 8 + w;
    int b    = p >> 13;

    // ---- load the 4 partial top-36 lists (lanes 0..31 + lanes 0..3) ----
    unsigned uA[NSPLIT], uB[NSPLIT];
    int      iA[NSPLIT], iB[NSPLIT];
    #pragma unroll
    for (int hh = 0; hh < NSPLIT; hh++) {
        size_t oh = ((size_t)hh * BN + p) * KNNK;
        uA[hh] = f2mono(g_pd[oh + lane]);
        iA[hh] = g_pi[oh + lane];
        uB[hh] = 0xFFFFFFFFu; iB[hh] = 0;
        if (lane < 4) {
            uB[hh] = f2mono(g_pd[oh + 32 + lane]);
            iB[hh] = g_pi[oh + 32 + lane];
        }
    }

    // ---- bit-bisection: V = 36th smallest of the 144 mono-uints ----
    unsigned prefix = 0;
    #pragma unroll
    for (int bit = 31; bit >= 0; bit--) {
        unsigned trial = prefix | ((1u << bit) - 1u);
        int cnt = 0;
        #pragma unroll
        for (int hh = 0; hh < NSPLIT; hh++) {
            cnt += __popc(__ballot_sync(FULL, uA[hh] <= trial));
            cnt += __popc(__ballot_sync(FULL, uB[hh] <= trial) & 0xFu);
        }
        if (cnt < KNNK) prefix |= (1u << bit);
    }
    const unsigned V = prefix;

    // ---- compaction of the <=V set into slots 0..35 ----
    unsigned lt = (1u << lane) - 1u;
    int base = 0;
    #pragma unroll
    for (int hh = 0; hh < NSPLIT; hh++) {
        unsigned mA = __ballot_sync(FULL, uA[hh] <= V);
        if (uA[hh] <= V) {
            int r = base + __popc(mA & lt);
            if (r < KNNK) ish[w][r] = iA[hh];
        }
        base += __popc(mA);
        unsigned mB = __ballot_sync(FULL, uB[hh] <= V) & 0xFu;
        if (lane < 4 && (uB[hh] <= V)) {
            int r = base + __popc(mB & lt);
            if (r < KNNK) ish[w][r] = iB[hh];
        }
        base += __popc(mB);
    }
    __syncwarp();

    int idxA = ish[w][lane];
    int idxB = (lane < 4) ? ish[w][32 + lane] : 0;

    // ---- attention logits (coalesced rows + shuffle reductions) ----
    const float* frow = feature + (size_t)p * 64;
    float2 q2 = *(const float2*)(frow + 2*lane);

    const float* fbase = feature + (size_t)b * NN * 64;
    float wA = 0.0f, wB = -3.4e38f;

    #pragma unroll
    for (int k = 0; k < KNNK; k++) {
        int j = (k < 32) ? __shfl_sync(FULL, idxA, k)
                         : __shfl_sync(FULL, idxB, k - 32);
        float2 f2 = *(const float2*)(fbase + (size_t)j * 64 + 2*lane);
        float part = fmaf(f2.x, q2.x, f2.y * q2.y);
        #pragma unroll
        for (int s = 16; s; s >>= 1)
            part += __shfl_xor_sync(FULL, part, s);
        if (k < 32) { if (lane == k)      wA = part; }
        else        { if (lane == k - 32) wB = part; }
    }

    float m = fmaxf(wA, (lane < 4) ? wB : -3.4e38f);
    #pragma unroll
    for (int s = 16; s; s >>= 1)
        m = fmaxf(m, __shfl_xor_sync(FULL, m, s));
    float eA = __expf(wA - m);
    float eB = (lane < 4) ? __expf(wB - m) : 0.0f;
    float ssum = eA + eB;
    #pragma unroll
    for (int s = 16; s; s >>= 1)
        ssum += __shfl_xor_sync(FULL, ssum, s);
    float inv = 1.0f / ssum;
    eA *= inv; eB *= inv;

    const float* vbase = g_vfeat + (size_t)b * NN * 64;
    float ox = 0.0f, oy = 0.0f;
    #pragma unroll
    for (int k = 0; k < KNNK; k++) {
        int j; float wk;
        if (k < 32) { j = __shfl_sync(FULL, idxA, k);      wk = __shfl_sync(FULL, eA, k); }
        else        { j = __shfl_sync(FULL, idxB, k - 32); wk = __shfl_sync(FULL, eB, k - 32); }
        float2 v2 = *(const float2*)(vbase + (size_t)j * 64 + 2*lane);
        ox = fmaf(wk, v2.x, ox);
        oy = fmaf(wk, v2.y, oy);
    }

    osh[w][2*lane]     = ox;
    osh[w][2*lane + 1] = oy;
    __syncwarp();
    float2 acc = *(const float2*)(bsuf + 2*lane);
    #pragma unroll 8
    for (int c = 0; c < 64; c++) {
        float oc = osh[w][c];
        float2 wv = *(const float2*)(Wsuf + c*64 + 2*lane);
        acc.x = fmaf(oc, wv.x, acc.x);
        acc.y = fmaf(oc, wv.y, acc.y);
    }
    *(float2*)(out + (size_t)p * 64 + 2*lane) = acc;
}

__global__ void tail_kernel(float* __restrict__ out, int out_size) {
    int i = BN*OUTD + blockIdx.x * blockDim.x + threadIdx.x;
    if (i < out_size) out[i] = (float)NN;
}

extern "C" void kernel_launch(void* const* d_in, const int* in_sizes, int n_in,
                              void* d_out, int out_size) {
    const float* feature = (const float*)d_in[0];
    const float* xyz     = (const float*)d_in[1];
    const float* Wv      = (const float*)d_in[2];
    const float* bv      = (const float*)d_in[3];
    const float* Wsuf    = (const float*)d_in[4];
    const float* bsuf    = (const float*)d_in[5];
    float* out = (float*)d_out;

    pack_xyz_kernel<<<(BN + 255) / 256, 256>>>(xyz);
    vfeat_kernel<<<BN / 4, 256>>>(feature, xyz, Wv, bv);
    dim3 kgrid(BN / KBLK, NSPLIT);
    knn_select_kernel<<<kgrid, KBLK>>>();
    knn_fallback_kernel<<<kgrid, KBLK>>>();
    attn_kernel<<<BN / 8, 256>>>(feature, Wsuf, bsuf, out);

    if (out_size > BN*OUTD) {
        int extra = out_size - BN*OUTD;
        tail_kernel<<<(extra + 255) / 256, 256>>>(out, out_size);
    }
}

// round 10
// speedup vs baseline: 1.7425x; 1.7425x over previous
#include <cuda_runtime.h>

#define BB 4
#define NN 8192
#define CC 64
#define OUTD 64
#define KNNK 36
#define BN (BB*NN)
#define KBLK 128
#define NSPLIT 2
#define HALF (NN/NSPLIT)       // 4096 candidates per split
#define TILE 256
#define SAMPLE 512             // phase-A sample size
#define PKEEP 16               // phase-A top-K (threshold = 16th smallest)
#define CAP 288                // survivor capacity per thread
#define FB_WARPS 2             // fallback warps per block

// Device scratch (allocation-free rule: __device__ globals)
__device__ float4 g_xyz4[BN];             // (sq, x, y, z) packed per point
__device__ float  g_vfeat[BN*OUTD];       // relu([feature,xyz] @ W_v + b_v)
__device__ float  g_pd[NSPLIT*BN*KNNK];   // partial top-36 distances
__device__ int    g_pi[NSPLIT*BN*KNNK];   // partial top-36 indices
__device__ int    g_nfail;                // flagged count
__device__ int    g_failq[NSPLIT*BN];     // flagged (h*BN+q) ids

// ---------------------------------------------------------------------------
__global__ void pack_xyz_kernel(const float* __restrict__ xyz) {
    int i = blockIdx.x * blockDim.x + threadIdx.x;
    if (i == 0) g_nfail = 0;
    if (i >= BN) return;
    float x = xyz[3*i], y = xyz[3*i+1], z = xyz[3*i+2];
    g_xyz4[i] = make_float4(x*x + y*y + z*z, x, y, z);
}

// ---------------------------------------------------------------------------
// v_feat = relu(concat([feature, xyz]) @ W_v + b_v)   (B,N,64)
// ---------------------------------------------------------------------------
__global__ __launch_bounds__(256) void vfeat_kernel(
    const float* __restrict__ feature,
    const float* __restrict__ xyz,
    const float* __restrict__ Wv,
    const float* __restrict__ bv)
{
    __shared__ float fsh[4][68];
    int sub = threadIdx.x >> 6;
    int t   = threadIdx.x & 63;
    int p   = blockIdx.x * 4 + sub;
    fsh[sub][t] = feature[p*64 + t];
    if (t < 3) fsh[sub][64 + t] = xyz[p*3 + t];
    __syncthreads();
    const float* f = fsh[sub];
    float acc = bv[t];
    #pragma unroll
    for (int c = 0; c < 67; c++)
        acc = fmaf(f[c], Wv[c*64 + t], acc);
    g_vfeat[p*64 + t] = fmaxf(acc, 0.0f);
}

// ---------------------------------------------------------------------------
// Equality-replace insert into a 36-entry register list.
// ---------------------------------------------------------------------------
__device__ __forceinline__ void topk_insert_eq(
    float d, int idx, float* kd, int* ki, float& worst)
{
    #pragma unroll
    for (int s = 0; s < KNNK; s++) {
        bool h = (kd[s] == worst);
        kd[s] = h ? d   : kd[s];
        ki[s] = h ? idx : ki[s];
    }
    float w = kd[0];
    #pragma unroll
    for (int s = 1; s < KNNK; s++)
        w = fmaxf(w, kd[s]);
    worst = w;
}

// ---------------------------------------------------------------------------
// KNN via threshold + collect over a half (blockIdx.y = half).
// Phase A: top-16 distances of first 512 candidates -> threshold T.
// Phase B: collect candidates with d <= T into local survivor arrays.
// Phase C: exact top-36 among survivors; out-of-range cnt -> queue for
//          warp-cooperative exact fallback.
// Exactness: if cnt = |{d<=T}| >= 36, the half's top-36 all satisfy d<=T.
// ---------------------------------------------------------------------------
__global__ __launch_bounds__(KBLK) void knn_select_kernel() {
    __shared__ float4 tile[TILE];
    const unsigned FULL = 0xffffffffu;

    int tid = threadIdx.x;
    int q = blockIdx.x * KBLK + tid;
    int h = blockIdx.y;
    int b = q >> 13;

    float4 me = g_xyz4[q];
    float nx = -2.0f * me.y, ny = -2.0f * me.z, nz = -2.0f * me.w;

    const float4* __restrict__ cand = g_xyz4 + b * NN + h * HALF;
    const int idx_off = h * HALF;

    // ---------------- Phase A: threshold = 16th smallest of first 512 -------
    float pd[PKEEP];
    float worstA;
    for (int base = 0; base < SAMPLE; base += TILE) {
        __syncthreads();
        tile[tid]        = cand[base + tid];
        tile[tid + KBLK] = cand[base + tid + KBLK];
        __syncthreads();

        if (base == 0) {
            #pragma unroll
            for (int s = 0; s < PKEEP; s++) {
                float4 c = tile[s];
                float d = fmaf(nx, c.y, c.x);
                d = fmaf(ny, c.z, d); d = fmaf(nz, c.w, d);
                pd[s] = d;
            }
            float w = pd[0];
            #pragma unroll
            for (int s = 1; s < PKEEP; s++) w = fmaxf(w, pd[s]);
            worstA = w;
        }

        for (int js = 0; js < TILE; js += 32) {
            unsigned m0 = 0, m1 = 0;
            #pragma unroll
            for (int jj = 0; jj < 16; jj++) {
                float4 c = tile[js + jj];
                float d = fmaf(nx, c.y, c.x);
                d = fmaf(ny, c.z, d); d = fmaf(nz, c.w, d);
                m0 |= (d < worstA) ? (1u << jj) : 0u;
            }
            #pragma unroll
            for (int jj = 16; jj < 32; jj++) {
                float4 c = tile[js + jj];
                float d = fmaf(nx, c.y, c.x);
                d = fmaf(ny, c.z, d); d = fmaf(nz, c.w, d);
                m1 |= (d < worstA) ? (1u << jj) : 0u;
            }
            unsigned mask = m0 | m1;
            if (base == 0 && js == 0) mask &= 0xFFFF0000u;  // first 16 filled

            if (__any_sync(FULL, mask != 0u)) {
                while (mask) {
                    int jj = __ffs(mask) - 1;
                    mask &= mask - 1;
                    float4 c = tile[js + jj];
                    float d = fmaf(nx, c.y, c.x);
                    d = fmaf(ny, c.z, d); d = fmaf(nz, c.w, d);
                    if (d < worstA) {
                        #pragma unroll
                        for (int s = 0; s < PKEEP; s++) {
                            bool hh = (pd[s] == worstA);
                            pd[s] = hh ? d : pd[s];
                        }
                        float w = pd[0];
                        #pragma unroll
                        for (int s = 1; s < PKEEP; s++) w = fmaxf(w, pd[s]);
                        worstA = w;
                    }
                }
            }
        }
    }
    const float T = worstA;   // fixed threshold for phase B

    // ---------------- Phase B: collect survivors (d <= T) -------------------
    float sd[CAP];
    int   si[CAP];
    int cnt = 0;

    for (int base = 0; base < HALF; base += TILE) {
        __syncthreads();
        tile[tid]        = cand[base + tid];
        tile[tid + KBLK] = cand[base + tid + KBLK];
        __syncthreads();

        for (int js = 0; js < TILE; js += 32) {
            unsigned m0 = 0, m1 = 0, m2 = 0, m3 = 0;
            #pragma unroll
            for (int jj = 0; jj < 8; jj++) {
                float4 c = tile[js + jj];
                float d = fmaf(nx, c.y, c.x);
                d = fmaf(ny, c.z, d); d = fmaf(nz, c.w, d);
                m0 |= (d <= T) ? (1u << jj) : 0u;
            }
            #pragma unroll
            for (int jj = 8; jj < 16; jj++) {
                float4 c = tile[js + jj];
                float d = fmaf(nx, c.y, c.x);
                d = fmaf(ny, c.z, d); d = fmaf(nz, c.w, d);
                m1 |= (d <= T) ? (1u << jj) : 0u;
            }
            #pragma unroll
            for (int jj = 16; jj < 24; jj++) {
                float4 c = tile[js + jj];
                float d = fmaf(nx, c.y, c.x);
                d = fmaf(ny, c.z, d); d = fmaf(nz, c.w, d);
                m2 |= (d <= T) ? (1u << jj) : 0u;
            }
            #pragma unroll
            for (int jj = 24; jj < 32; jj++) {
                float4 c = tile[js + jj];
                float d = fmaf(nx, c.y, c.x);
                d = fmaf(ny, c.z, d); d = fmaf(nz, c.w, d);
                m3 |= (d <= T) ? (1u << jj) : 0u;
            }
            unsigned mask = (m0 | m1) | (m2 | m3);
            if (__any_sync(FULL, mask != 0u)) {
                while (mask) {
                    int jj = __ffs(mask) - 1;
                    mask &= mask - 1;
                    float4 c = tile[js + jj];
                    float d = fmaf(nx, c.y, c.x);
                    d = fmaf(ny, c.z, d); d = fmaf(nz, c.w, d);
                    if (cnt < CAP) { sd[cnt] = d; si[cnt] = idx_off + base + js + jj; }
                    cnt++;
                }
            }
        }
    }

    // ---------------- Phase C: exact top-36 among survivors -----------------
    bool fail = (cnt < KNNK) || (cnt > CAP);
    if (fail) {
        int slot = atomicAdd(&g_nfail, 1);
        g_failq[slot] = h * BN + q;
    } else {
        float kd[KNNK];
        int   ki[KNNK];
        #pragma unroll
        for (int s = 0; s < KNNK; s++) { kd[s] = sd[s]; ki[s] = si[s]; }
        float worst = kd[0];
        #pragma unroll
        for (int s = 1; s < KNNK; s++) worst = fmaxf(worst, kd[s]);

        for (int it = KNNK; it < cnt; it++) {
            float d = sd[it];
            if (d < worst)
                topk_insert_eq(d, si[it], kd, ki, worst);
        }

        size_t o = ((size_t)h * BN + q) * KNNK;
        #pragma unroll
        for (int s = 0; s < KNNK; s++) {
            g_pd[o + s] = kd[s];
            g_pi[o + s] = ki[s];
        }
    }
}

// ---------------------------------------------------------------------------
// Order-preserving float <-> uint maps for bit-bisection selection.
// ---------------------------------------------------------------------------
__device__ __forceinline__ unsigned f2mono(float f) {
    unsigned u = __float_as_uint(f);
    return (u & 0x80000000u) ? ~u : (u | 0x80000000u);
}
__device__ __forceinline__ float mono2f(unsigned m) {
    unsigned u = (m & 0x80000000u) ? (m ^ 0x80000000u) : ~m;
    return __uint_as_float(u);
}

// ---------------------------------------------------------------------------
// Warp-cooperative EXACT fallback. Each flagged (q,half) pair is handled by
// one warp: distances cached in smem (mono-uints), 32-iteration ballot
// bisection finds the exact 36th-smallest value V, ballot-prefix compaction
// writes 36 (value,index) pairs. 256 blocks x 2 warps grid-stride the queue.
// ---------------------------------------------------------------------------
__global__ __launch_bounds__(FB_WARPS*32) void knn_fallback_kernel() {
    __shared__ unsigned um[FB_WARPS][HALF];     // 2 x 16KB
    const unsigned FULL = 0xffffffffu;
    int wid  = threadIdx.x >> 5;
    int lane = threadIdx.x & 31;
    int warp_global = blockIdx.x * FB_WARPS + wid;
    int nwarps = gridDim.x * FB_WARPS;

    int nf = g_nfail;
    for (int t = warp_global; t < nf; t += nwarps) {
        int id = g_failq[t];
        int h = id / BN;
        int q = id - h * BN;
        int b = q >> 13;

        float4 me = g_xyz4[q];
        float nx = -2.0f * me.y, ny = -2.0f * me.z, nz = -2.0f * me.w;
        const float4* __restrict__ cand = g_xyz4 + b * NN + h * HALF;

        // compute + cache mono distances (coalesced float4 loads)
        for (int i = 0; i < HALF/32; i++) {
            int j = lane + 32*i;
            float4 c = cand[j];
            float d = fmaf(nx, c.y, c.x);
            d = fmaf(ny, c.z, d); d = fmaf(nz, c.w, d);
            um[wid][j] = f2mono(d);
        }
        __syncwarp();

        // bisection: V = 36th smallest mono-uint of the 4096
        unsigned prefix = 0;
        for (int bit = 31; bit >= 0; bit--) {
            unsigned trial = prefix | ((1u << bit) - 1u);
            int cnt = 0;
            for (int i = 0; i < HALF/32; i++)
                cnt += (um[wid][lane + 32*i] <= trial) ? 1 : 0;
            #pragma unroll
            for (int s = 16; s; s >>= 1)
                cnt += __shfl_xor_sync(FULL, cnt, s);
            if (cnt < KNNK) prefix |= (1u << bit);
        }
        const unsigned V = prefix;

        // compact first 36 entries with u <= V
        size_t o = ((size_t)h * BN + q) * KNNK;
        unsigned lt = (1u << lane) - 1u;
        int base = 0;
        for (int i = 0; i < HALF/32 && base < KNNK; i++) {
            int j = lane + 32*i;
            unsigned u = um[wid][j];
            bool hit = (u <= V);
            unsigned m = __ballot_sync(FULL, hit);
            if (hit) {
                int r = base + __popc(m & lt);
                if (r < KNNK) {
                    g_pd[o + r] = mono2f(u);
                    g_pi[o + r] = h * HALF + j;
                }
            }
            base += __popc(m);
        }
        __syncwarp();
    }
}

// ---------------------------------------------------------------------------
// Fused 2-way merge + attention + suffix GEMM. Warp per point.
// Merge: exact top-36 of the 72 partials via ballot bit-bisection + compaction.
// ---------------------------------------------------------------------------
__global__ __launch_bounds__(256) void attn_kernel(
    const float* __restrict__ feature,
    const float* __restrict__ Wsuf,
    const float* __restrict__ bsuf,
    float* __restrict__ out)
{
    __shared__ int   ish[8][40];
    __shared__ float osh[8][64];
    const unsigned FULL = 0xffffffffu;
    int w    = threadIdx.x >> 5;
    int lane = threadIdx.x & 31;
    int p    = blockIdx.x * 8 + w;
    int b    = p >> 13;

    size_t o0 = (size_t)p * KNNK;
    size_t o1 = (size_t)BN * KNNK + o0;
    unsigned uA0 = f2mono(g_pd[o0 + lane]);
    unsigned uA1 = f2mono(g_pd[o1 + lane]);
    unsigned uB0 = 0xFFFFFFFFu, uB1 = 0xFFFFFFFFu;
    int iA0 = g_pi[o0 + lane];
    int iA1 = g_pi[o1 + lane];
    int iB0 = 0, iB1 = 0;
    if (lane < 4) {
        uB0 = f2mono(g_pd[o0 + 32 + lane]);  iB0 = g_pi[o0 + 32 + lane];
        uB1 = f2mono(g_pd[o1 + 32 + lane]);  iB1 = g_pi[o1 + 32 + lane];
    }

    unsigned prefix = 0;
    #pragma unroll
    for (int bit = 31; bit >= 0; bit--) {
        unsigned trial = prefix | ((1u << bit) - 1u);
        int cnt = __popc(__ballot_sync(FULL, uA0 <= trial))
                + __popc(__ballot_sync(FULL, uB0 <= trial) & 0xFu)
                + __popc(__ballot_sync(FULL, uA1 <= trial))
                + __popc(__ballot_sync(FULL, uB1 <= trial) & 0xFu);
        if (cnt < KNNK) prefix |= (1u << bit);
    }
    const unsigned V = prefix;

    unsigned mA0 = __ballot_sync(FULL, uA0 <= V);
    unsigned mB0 = __ballot_sync(FULL, uB0 <= V) & 0xFu;
    unsigned mA1 = __ballot_sync(FULL, uA1 <= V);
    unsigned mB1 = __ballot_sync(FULL, uB1 <= V) & 0xFu;
    int baseB0 = __popc(mA0);
    int baseA1 = baseB0 + __popc(mB0);
    int baseB1 = baseA1 + __popc(mA1);
    unsigned lt = (1u << lane) - 1u;

    if (uA0 <= V) {
        int r = __popc(mA0 & lt);
        if (r < KNNK) ish[w][r] = iA0;
    }
    if (lane < 4 && (uB0 <= V)) {
        int r = baseB0 + __popc(mB0 & lt);
        if (r < KNNK) ish[w][r] = iB0;
    }
    if (uA1 <= V) {
        int r = baseA1 + __popc(mA1 & lt);
        if (r < KNNK) ish[w][r] = iA1;
    }
    if (lane < 4 && (uB1 <= V)) {
        int r = baseB1 + __popc(mB1 & lt);
        if (r < KNNK) ish[w][r] = iB1;
    }
    __syncwarp();

    int idxA = ish[w][lane];
    int idxB = (lane < 4) ? ish[w][32 + lane] : 0;

    const float* frow = feature + (size_t)p * 64;
    float2 q2 = *(const float2*)(frow + 2*lane);

    const float* fbase = feature + (size_t)b * NN * 64;
    float wA = 0.0f, wB = -3.4e38f;

    #pragma unroll
    for (int k = 0; k < KNNK; k++) {
        int j = (k < 32) ? __shfl_sync(FULL, idxA, k)
                         : __shfl_sync(FULL, idxB, k - 32);
        float2 f2 = *(const float2*)(fbase + (size_t)j * 64 + 2*lane);
        float part = fmaf(f2.x, q2.x, f2.y * q2.y);
        #pragma unroll
        for (int s = 16; s; s >>= 1)
            part += __shfl_xor_sync(FULL, part, s);
        if (k < 32) { if (lane == k)      wA = part; }
        else        { if (lane == k - 32) wB = part; }
    }

    float m = fmaxf(wA, (lane < 4) ? wB : -3.4e38f);
    #pragma unroll
    for (int s = 16; s; s >>= 1)
        m = fmaxf(m, __shfl_xor_sync(FULL, m, s));
    float eA = __expf(wA - m);
    float eB = (lane < 4) ? __expf(wB - m) : 0.0f;
    float ssum = eA + eB;
    #pragma unroll
    for (int s = 16; s; s >>= 1)
        ssum += __shfl_xor_sync(FULL, ssum, s);
    float inv = 1.0f / ssum;
    eA *= inv; eB *= inv;

    const float* vbase = g_vfeat + (size_t)b * NN * 64;
    float ox = 0.0f, oy = 0.0f;
    #pragma unroll
    for (int k = 0; k < KNNK; k++) {
        int j; float wk;
        if (k < 32) { j = __shfl_sync(FULL, idxA, k);      wk = __shfl_sync(FULL, eA, k); }
        else        { j = __shfl_sync(FULL, idxB, k - 32); wk = __shfl_sync(FULL, eB, k - 32); }
        float2 v2 = *(const float2*)(vbase + (size_t)j * 64 + 2*lane);
        ox = fmaf(wk, v2.x, ox);
        oy = fmaf(wk, v2.y, oy);
    }

    osh[w][2*lane]     = ox;
    osh[w][2*lane + 1] = oy;
    __syncwarp();
    float2 acc = *(const float2*)(bsuf + 2*lane);
    #pragma unroll 8
    for (int c = 0; c < 64; c++) {
        float oc = osh[w][c];
        float2 wv = *(const float2*)(Wsuf + c*64 + 2*lane);
        acc.x = fmaf(oc, wv.x, acc.x);
        acc.y = fmaf(oc, wv.y, acc.y);
    }
    *(float2*)(out + (size_t)p * 64 + 2*lane) = acc;
}

__global__ void tail_kernel(float* __restrict__ out, int out_size) {
    int i = BN*OUTD + blockIdx.x * blockDim.x + threadIdx.x;
    if (i < out_size) out[i] = (float)NN;
}

extern "C" void kernel_launch(void* const* d_in, const int* in_sizes, int n_in,
                              void* d_out, int out_size) {
    const float* feature = (const float*)d_in[0];
    const float* xyz     = (const float*)d_in[1];
    const float* Wv      = (const float*)d_in[2];
    const float* bv      = (const float*)d_in[3];
    const float* Wsuf    = (const float*)d_in[4];
    const float* bsuf    = (const float*)d_in[5];
    float* out = (float*)d_out;

    pack_xyz_kernel<<<(BN + 255) / 256, 256>>>(xyz);
    vfeat_kernel<<<BN / 4, 256>>>(feature, xyz, Wv, bv);
    dim3 kgrid(BN / KBLK, NSPLIT);
    knn_select_kernel<<<kgrid, KBLK>>>();
    knn_fallback_kernel<<<256, FB_WARPS*32>>>();
    attn_kernel<<<BN / 8, 256>>>(feature, Wsuf, bsuf, out);

    if (out_size > BN*OUTD) {
        int extra = out_size - BN*OUTD;
        tail_kernel<<<(extra + 255) / 256, 256>>>(out, out_size);
    }
}

// round 11
// speedup vs baseline: 1.7591x; 1.0095x over previous
#include <cuda_runtime.h>

#define BB 4
#define NN 8192
#define CC 64
#define OUTD 64
#define KNNK 36
#define BN (BB*NN)
#define KBLK 128
#define NSPLIT 4
#define QPART (NN/NSPLIT)      // 2048 candidates per split
#define TILE 256
#define SAMPLE 512             // threshold sample size
#define PKEEP 16               // threshold = 16th smallest of sample
#define CAP 160                // survivor capacity per thread per quarter
#define FINF 3.402823466e38f

// Device scratch (allocation-free rule: __device__ globals)
__device__ float4 g_xyz4[BN];             // (sq, x, y, z) packed per point
__device__ float  g_vfeat[BN*OUTD];       // relu([feature,xyz] @ W_v + b_v)
__device__ float  g_T[BN];                // per-query collect threshold
__device__ float  g_pd[NSPLIT*BN*KNNK];   // partial top-36 distances (INF pad)
__device__ int    g_pi[NSPLIT*BN*KNNK];   // partial top-36 indices (batch-rel)
__device__ int    g_cnt[NSPLIT*BN];       // per (quarter,q) raw survivor count

// ---------------------------------------------------------------------------
__global__ void pack_xyz_kernel(const float* __restrict__ xyz) {
    int i = blockIdx.x * blockDim.x + threadIdx.x;
    if (i >= BN) return;
    float x = xyz[3*i], y = xyz[3*i+1], z = xyz[3*i+2];
    g_xyz4[i] = make_float4(x*x + y*y + z*z, x, y, z);
}

// ---------------------------------------------------------------------------
// v_feat = relu(concat([feature, xyz]) @ W_v + b_v)   (B,N,64)
// ---------------------------------------------------------------------------
__global__ __launch_bounds__(256) void vfeat_kernel(
    const float* __restrict__ feature,
    const float* __restrict__ xyz,
    const float* __restrict__ Wv,
    const float* __restrict__ bv)
{
    __shared__ float fsh[4][68];
    int sub = threadIdx.x >> 6;
    int t   = threadIdx.x & 63;
    int p   = blockIdx.x * 4 + sub;
    fsh[sub][t] = feature[p*64 + t];
    if (t < 3) fsh[sub][64 + t] = xyz[p*3 + t];
    __syncthreads();
    const float* f = fsh[sub];
    float acc = bv[t];
    #pragma unroll
    for (int c = 0; c < 67; c++)
        acc = fmaf(f[c], Wv[c*64 + t], acc);
    g_vfeat[p*64 + t] = fmaxf(acc, 0.0f);
}

// ---------------------------------------------------------------------------
// Equality-replace insert into a 36-entry register list.
// ---------------------------------------------------------------------------
__device__ __forceinline__ void topk_insert_eq(
    float d, int idx, float* kd, int* ki, float& worst)
{
    #pragma unroll
    for (int s = 0; s < KNNK; s++) {
        bool h = (kd[s] == worst);
        kd[s] = h ? d   : kd[s];
        ki[s] = h ? idx : ki[s];
    }
    float w = kd[0];
    #pragma unroll
    for (int s = 1; s < KNNK; s++)
        w = fmaxf(w, kd[s]);
    worst = w;
}

// ---------------------------------------------------------------------------
// Threshold kernel: per query, T = 16th smallest distance among the batch's
// first 512 candidates (smem-tiled, bitmask-gated inserts).
// Expected |{d<=T}| over full N ~ 256 +- 60 -> P(<36) ~ 1e-4.
// ---------------------------------------------------------------------------
__global__ __launch_bounds__(KBLK) void knn_thresh_kernel() {
    __shared__ float4 tile[TILE];
    const unsigned FULL = 0xffffffffu;

    int tid = threadIdx.x;
    int q = blockIdx.x * KBLK + tid;
    int b = q >> 13;

    float4 me = g_xyz4[q];
    float nx = -2.0f * me.y, ny = -2.0f * me.z, nz = -2.0f * me.w;
    const float4* __restrict__ cand = g_xyz4 + b * NN;

    float pd[PKEEP];
    float worstA;
    for (int base = 0; base < SAMPLE; base += TILE) {
        __syncthreads();
        tile[tid]        = cand[base + tid];
        tile[tid + KBLK] = cand[base + tid + KBLK];
        __syncthreads();

        if (base == 0) {
            #pragma unroll
            for (int s = 0; s < PKEEP; s++) {
                float4 c = tile[s];
                float d = fmaf(nx, c.y, c.x);
                d = fmaf(ny, c.z, d); d = fmaf(nz, c.w, d);
                pd[s] = d;
            }
            float w = pd[0];
            #pragma unroll
            for (int s = 1; s < PKEEP; s++) w = fmaxf(w, pd[s]);
            worstA = w;
        }

        for (int js = 0; js < TILE; js += 32) {
            unsigned m0 = 0, m1 = 0;
            #pragma unroll
            for (int jj = 0; jj < 16; jj++) {
                float4 c = tile[js + jj];
                float d = fmaf(nx, c.y, c.x);
                d = fmaf(ny, c.z, d); d = fmaf(nz, c.w, d);
                m0 |= (d < worstA) ? (1u << jj) : 0u;
            }
            #pragma unroll
            for (int jj = 16; jj < 32; jj++) {
                float4 c = tile[js + jj];
                float d = fmaf(nx, c.y, c.x);
                d = fmaf(ny, c.z, d); d = fmaf(nz, c.w, d);
                m1 |= (d < worstA) ? (1u << jj) : 0u;
            }
            unsigned mask = m0 | m1;
            if (base == 0 && js == 0) mask &= 0xFFFF0000u;  // first 16 filled

            if (__any_sync(FULL, mask != 0u)) {
                while (mask) {
                    int jj = __ffs(mask) - 1;
                    mask &= mask - 1;
                    float4 c = tile[js + jj];
                    float d = fmaf(nx, c.y, c.x);
                    d = fmaf(ny, c.z, d); d = fmaf(nz, c.w, d);
                    if (d < worstA) {
                        #pragma unroll
                        for (int s = 0; s < PKEEP; s++) {
                            bool hh = (pd[s] == worstA);
                            pd[s] = hh ? d : pd[s];
                        }
                        float w = pd[0];
                        #pragma unroll
                        for (int s = 1; s < PKEEP; s++) w = fmaxf(w, pd[s]);
                        worstA = w;
                    }
                }
            }
        }
    }
    g_T[q] = worstA;
}

// ---------------------------------------------------------------------------
// Collect + per-quarter top-36 (blockIdx.y = quarter). Uses the shared per-
// query threshold T. Quarters with <36 survivors pad with +INF (the global
// survivor-count check lives in the fallback kernel).
// ---------------------------------------------------------------------------
__global__ __launch_bounds__(KBLK) void knn_select_kernel() {
    __shared__ float4 tile[TILE];
    const unsigned FULL = 0xffffffffu;

    int tid = threadIdx.x;
    int q = blockIdx.x * KBLK + tid;
    int h = blockIdx.y;
    int b = q >> 13;

    float4 me = g_xyz4[q];
    float nx = -2.0f * me.y, ny = -2.0f * me.z, nz = -2.0f * me.w;
    const float T = g_T[q];

    const float4* __restrict__ cand = g_xyz4 + b * NN + h * QPART;
    const int idx_off = h * QPART;

    float sd[CAP];
    int   si[CAP];
    int cnt = 0;

    for (int base = 0; base < QPART; base += TILE) {
        __syncthreads();
        tile[tid]        = cand[base + tid];
        tile[tid + KBLK] = cand[base + tid + KBLK];
        __syncthreads();

        for (int js = 0; js < TILE; js += 32) {
            unsigned m0 = 0, m1 = 0, m2 = 0, m3 = 0;
            #pragma unroll
            for (int jj = 0; jj < 8; jj++) {
                float4 c = tile[js + jj];
                float d = fmaf(nx, c.y, c.x);
                d = fmaf(ny, c.z, d); d = fmaf(nz, c.w, d);
                m0 |= (d <= T) ? (1u << jj) : 0u;
            }
            #pragma unroll
            for (int jj = 8; jj < 16; jj++) {
                float4 c = tile[js + jj];
                float d = fmaf(nx, c.y, c.x);
                d = fmaf(ny, c.z, d); d = fmaf(nz, c.w, d);
                m1 |= (d <= T) ? (1u << jj) : 0u;
            }
            #pragma unroll
            for (int jj = 16; jj < 24; jj++) {
                float4 c = tile[js + jj];
                float d = fmaf(nx, c.y, c.x);
                d = fmaf(ny, c.z, d); d = fmaf(nz, c.w, d);
                m2 |= (d <= T) ? (1u << jj) : 0u;
            }
            #pragma unroll
            for (int jj = 24; jj < 32; jj++) {
                float4 c = tile[js + jj];
                float d = fmaf(nx, c.y, c.x);
                d = fmaf(ny, c.z, d); d = fmaf(nz, c.w, d);
                m3 |= (d <= T) ? (1u << jj) : 0u;
            }
            unsigned mask = (m0 | m1) | (m2 | m3);
            if (__any_sync(FULL, mask != 0u)) {
                while (mask) {
                    int jj = __ffs(mask) - 1;
                    mask &= mask - 1;
                    float4 c = tile[js + jj];
                    float d = fmaf(nx, c.y, c.x);
                    d = fmaf(ny, c.z, d); d = fmaf(nz, c.w, d);
                    if (cnt < CAP) { sd[cnt] = d; si[cnt] = idx_off + base + js + jj; }
                    cnt++;
                }
            }
        }
    }

    g_cnt[(size_t)h * BN + q] = cnt;
    size_t o = ((size_t)h * BN + q) * KNNK;

    if (cnt <= KNNK) {
        // write all survivors, pad with +INF
        for (int s = 0; s < KNNK; s++) {
            bool v = (s < cnt);
            g_pd[o + s] = v ? sd[s] : FINF;
            g_pi[o + s] = v ? si[s] : 0;
        }
    } else if (cnt <= CAP) {
        float kd[KNNK];
        int   ki[KNNK];
        #pragma unroll
        for (int s = 0; s < KNNK; s++) { kd[s] = sd[s]; ki[s] = si[s]; }
        float worst = kd[0];
        #pragma unroll
        for (int s = 1; s < KNNK; s++) worst = fmaxf(worst, kd[s]);

        for (int it = KNNK; it < cnt; it++) {
            float d = sd[it];
            if (d < worst)
                topk_insert_eq(d, si[it], kd, ki, worst);
        }
        #pragma unroll
        for (int s = 0; s < KNNK; s++) {
            g_pd[o + s] = kd[s];
            g_pi[o + s] = ki[s];
        }
    }
    // cnt > CAP: quarter data unusable; fallback (triggered by g_cnt) rewrites.
}

// ---------------------------------------------------------------------------
// Order-preserving float <-> uint maps for bit-bisection selection.
// ---------------------------------------------------------------------------
__device__ __forceinline__ unsigned f2mono(float f) {
    unsigned u = __float_as_uint(f);
    return (u & 0x80000000u) ? ~u : (u | 0x80000000u);
}
__device__ __forceinline__ float mono2f(unsigned m) {
    unsigned u = (m & 0x80000000u) ? (m ^ 0x80000000u) : ~m;
    return __uint_as_float(u);
}

// ---------------------------------------------------------------------------
// Fallback: per-query exactness check (total survivors >= 36 and all quarter
// counts <= CAP); failures (expected ~3/run) get an exact whole-N warp
// bisection. Result overwrites quarter-0 list; quarters 1-3 padded to +INF.
// ---------------------------------------------------------------------------
__global__ __launch_bounds__(KBLK) void knn_fallback_kernel() {
    __shared__ unsigned um[NN];            // 32KB distance cache
    __shared__ int fq[KBLK];
    __shared__ int fn;
    const unsigned FULL = 0xffffffffu;

    int tid = threadIdx.x;
    int q = blockIdx.x * KBLK + tid;

    if (tid == 0) fn = 0;
    __syncthreads();

    int total = 0;
    bool over = false;
    #pragma unroll
    for (int h = 0; h < NSPLIT; h++) {
        int c = g_cnt[(size_t)h * BN + q];
        total += c;
        over |= (c > CAP);
    }
    if (total < KNNK || over) {
        int slot = atomicAdd(&fn, 1);
        fq[slot] = q;
    }
    __syncthreads();

    int nf = fn;
    for (int t = 0; t < nf; t++) {
        int fqq = fq[t];
        int b = fqq >> 13;
        float4 me = g_xyz4[fqq];
        float nx = -2.0f * me.y, ny = -2.0f * me.z, nz = -2.0f * me.w;
        const float4* __restrict__ cand = g_xyz4 + b * NN;

        // all 128 threads fill the distance cache (coalesced)
        for (int i = tid; i < NN; i += KBLK) {
            float4 c = cand[i];
            float d = fmaf(nx, c.y, c.x);
            d = fmaf(ny, c.z, d); d = fmaf(nz, c.w, d);
            um[i] = f2mono(d);
        }
        __syncthreads();

        // warp 0: bisection for the exact 36th smallest, then compaction
        if (tid < 32) {
            int lane = tid;
            unsigned prefix = 0;
            for (int bit = 31; bit >= 0; bit--) {
                unsigned trial = prefix | ((1u << bit) - 1u);
                int cnt = 0;
                for (int i = 0; i < NN/32; i++)
                    cnt += (um[lane + 32*i] <= trial) ? 1 : 0;
                #pragma unroll
                for (int s = 16; s; s >>= 1)
                    cnt += __shfl_xor_sync(FULL, cnt, s);
                if (cnt < KNNK) prefix |= (1u << bit);
            }
            const unsigned V = prefix;

            size_t o = (size_t)fqq * KNNK;
            unsigned lt = (1u << lane) - 1u;
            int base = 0;
            for (int i = 0; i < NN/32 && base < KNNK; i++) {
                int j = lane + 32*i;
                unsigned u = um[j];
                bool hit = (u <= V);
                unsigned m = __ballot_sync(FULL, hit);
                if (hit) {
                    int r = base + __popc(m & lt);
                    if (r < KNNK) {
                        g_pd[o + r] = mono2f(u);
                        g_pi[o + r] = j;
                    }
                }
                base += __popc(m);
            }
            // pad quarters 1..3 with +INF
            for (int h = 1; h < NSPLIT; h++) {
                size_t oh = ((size_t)h * BN + fqq) * KNNK;
                for (int s = lane; s < KNNK; s += 32) {
                    g_pd[oh + s] = FINF;
                    g_pi[oh + s] = 0;
                }
            }
        }
        __syncthreads();
    }
}

// ---------------------------------------------------------------------------
// Fused 4-way merge + attention + suffix GEMM. Warp per point.
// Merge: exact top-36 of 144 (=4x36, INF-padded) partials via warp ballot
// bit-bisection, then ballot-prefix compaction into 36 smem slots.
// ---------------------------------------------------------------------------
__global__ __launch_bounds__(256) void attn_kernel(
    const float* __restrict__ feature,
    const float* __restrict__ Wsuf,
    const float* __restrict__ bsuf,
    float* __restrict__ out)
{
    __shared__ int   ish[8][40];
    __shared__ float osh[8][64];
    const unsigned FULL = 0xffffffffu;
    int w    = threadIdx.x >> 5;
    int lane = threadIdx.x & 31;
    int p    = blockIdx.x * 8 + w;
    int b    = p >> 13;

    unsigned uA[NSPLIT], uB[NSPLIT];
    int      iA[NSPLIT], iB[NSPLIT];
    #pragma unroll
    for (int hh = 0; hh < NSPLIT; hh++) {
        size_t oh = ((size_t)hh * BN + p) * KNNK;
        uA[hh] = f2mono(g_pd[oh + lane]);
        iA[hh] = g_pi[oh + lane];
        uB[hh] = 0xFFFFFFFFu; iB[hh] = 0;
        if (lane < 4) {
            uB[hh] = f2mono(g_pd[oh + 32 + lane]);
            iB[hh] = g_pi[oh + 32 + lane];
        }
    }

    unsigned prefix = 0;
    #pragma unroll
    for (int bit = 31; bit >= 0; bit--) {
        unsigned trial = prefix | ((1u << bit) - 1u);
        int cnt = 0;
        #pragma unroll
        for (int hh = 0; hh < NSPLIT; hh++) {
            cnt += __popc(__ballot_sync(FULL, uA[hh] <= trial));
            cnt += __popc(__ballot_sync(FULL, uB[hh] <= trial) & 0xFu);
        }
        if (cnt < KNNK) prefix |= (1u << bit);
    }
    const unsigned V = prefix;

    unsigned lt = (1u << lane) - 1u;
    int base = 0;
    #pragma unroll
    for (int hh = 0; hh < NSPLIT; hh++) {
        unsigned mA = __ballot_sync(FULL, uA[hh] <= V);
        if (uA[hh] <= V) {
            int r = base + __popc(mA & lt);
            if (r < KNNK) ish[w][r] = iA[hh];
        }
        base += __popc(mA);
        unsigned mB = __ballot_sync(FULL, uB[hh] <= V) & 0xFu;
        if (lane < 4 && (uB[hh] <= V)) {
            int r = base + __popc(mB & lt);
            if (r < KNNK) ish[w][r] = iB[hh];
        }
        base += __popc(mB);
    }
    __syncwarp();

    int idxA = ish[w][lane];
    int idxB = (lane < 4) ? ish[w][32 + lane] : 0;

    const float* frow = feature + (size_t)p * 64;
    float2 q2 = *(const float2*)(frow + 2*lane);

    const float* fbase = feature + (size_t)b * NN * 64;
    float wA = 0.0f, wB = -3.4e38f;

    #pragma unroll
    for (int k = 0; k < KNNK; k++) {
        int j = (k < 32) ? __shfl_sync(FULL, idxA, k)
                         : __shfl_sync(FULL, idxB, k - 32);
        float2 f2 = *(const float2*)(fbase + (size_t)j * 64 + 2*lane);
        float part = fmaf(f2.x, q2.x, f2.y * q2.y);
        #pragma unroll
        for (int s = 16; s; s >>= 1)
            part += __shfl_xor_sync(FULL, part, s);
        if (k < 32) { if (lane == k)      wA = part; }
        else        { if (lane == k - 32) wB = part; }
    }

    float m = fmaxf(wA, (lane < 4) ? wB : -3.4e38f);
    #pragma unroll
    for (int s = 16; s; s >>= 1)
        m = fmaxf(m, __shfl_xor_sync(FULL, m, s));
    float eA = __expf(wA - m);
    float eB = (lane < 4) ? __expf(wB - m) : 0.0f;
    float ssum = eA + eB;
    #pragma unroll
    for (int s = 16; s; s >>= 1)
        ssum += __shfl_xor_sync(FULL, ssum, s);
    float inv = 1.0f / ssum;
    eA *= inv; eB *= inv;

    const float* vbase = g_vfeat + (size_t)b * NN * 64;
    float ox = 0.0f, oy = 0.0f;
    #pragma unroll
    for (int k = 0; k < KNNK; k++) {
        int j; float wk;
        if (k < 32) { j = __shfl_sync(FULL, idxA, k);      wk = __shfl_sync(FULL, eA, k); }
        else        { j = __shfl_sync(FULL, idxB, k - 32); wk = __shfl_sync(FULL, eB, k - 32); }
        float2 v2 = *(const float2*)(vbase + (size_t)j * 64 + 2*lane);
        ox = fmaf(wk, v2.x, ox);
        oy = fmaf(wk, v2.y, oy);
    }

    osh[w][2*lane]     = ox;
    osh[w][2*lane + 1] = oy;
    __syncwarp();
    float2 acc = *(const float2*)(bsuf + 2*lane);
    #pragma unroll 8
    for (int c = 0; c < 64; c++) {
        float oc = osh[w][c];
        float2 wv = *(const float2*)(Wsuf + c*64 + 2*lane);
        acc.x = fmaf(oc, wv.x, acc.x);
        acc.y = fmaf(oc, wv.y, acc.y);
    }
    *(float2*)(out + (size_t)p * 64 + 2*lane) = acc;
}

__global__ void tail_kernel(float* __restrict__ out, int out_size) {
    int i = BN*OUTD + blockIdx.x * blockDim.x + threadIdx.x;
    if (i < out_size) out[i] = (float)NN;
}

extern "C" void kernel_launch(void* const* d_in, const int* in_sizes, int n_in,
                              void* d_out, int out_size) {
    const float* feature = (const float*)d_in[0];
    const float* xyz     = (const float*)d_in[1];
    const float* Wv      = (const float*)d_in[2];
    const float* bv      = (const float*)d_in[3];
    const float* Wsuf    = (const float*)d_in[4];
    const float* bsuf    = (const float*)d_in[5];
    float* out = (float*)d_out;

    pack_xyz_kernel<<<(BN + 255) / 256, 256>>>(xyz);
    vfeat_kernel<<<BN / 4, 256>>>(feature, xyz, Wv, bv);
    knn_thresh_kernel<<<BN / KBLK, KBLK>>>();
    dim3 kgrid(BN / KBLK, NSPLIT);
    knn_select_kernel<<<kgrid, KBLK>>>();
    knn_fallback_kernel<<<BN / KBLK, KBLK>>>();
    attn_kernel<<<BN / 8, 256>>>(feature, Wsuf, bsuf, out);

    if (out_size > BN*OUTD) {
        int extra = out_size - BN*OUTD;
        tail_kernel<<<(extra + 255) / 256, 256>>>(out, out_size);
    }
}

// round 12
// speedup vs baseline: 1.8529x; 1.0533x over previous
#include <cuda_runtime.h>

#define BB 4
#define NN 8192
#define CC 64
#define OUTD 64
#define KNNK 36
#define BN (BB*NN)
#define KBLK 128
#define NSPLIT 4
#define QPART (NN/NSPLIT)      // 2048 candidates per split
#define SAMPLE 512             // threshold sample size
#define PKEEP 14               // threshold = 14th smallest of sample
#define CAP 128                // survivor capacity per thread per quarter
#define FINF 3.402823466e38f

// Device scratch (allocation-free rule: __device__ globals)
__device__ float4 g_xyz4[BN];             // (sq, x, y, z) packed per point
__device__ float  g_vfeat[BN*OUTD];       // relu([feature,xyz] @ W_v + b_v)
__device__ float  g_T[BN];                // per-query collect threshold
__device__ float  g_pd[NSPLIT*BN*KNNK];   // partial top-36 distances (INF pad)
__device__ int    g_pi[NSPLIT*BN*KNNK];   // partial top-36 indices (batch-rel)
__device__ int    g_cnt[NSPLIT*BN];       // per (quarter,q) raw survivor count

// ---------------------------------------------------------------------------
__global__ void pack_xyz_kernel(const float* __restrict__ xyz) {
    int i = blockIdx.x * blockDim.x + threadIdx.x;
    if (i >= BN) return;
    float x = xyz[3*i], y = xyz[3*i+1], z = xyz[3*i+2];
    g_xyz4[i] = make_float4(x*x + y*y + z*z, x, y, z);
}

// ---------------------------------------------------------------------------
// v_feat = relu(concat([feature, xyz]) @ W_v + b_v)   (B,N,64)
// ---------------------------------------------------------------------------
__global__ __launch_bounds__(256) void vfeat_kernel(
    const float* __restrict__ feature,
    const float* __restrict__ xyz,
    const float* __restrict__ Wv,
    const float* __restrict__ bv)
{
    __shared__ float fsh[4][68];
    int sub = threadIdx.x >> 6;
    int t   = threadIdx.x & 63;
    int p   = blockIdx.x * 4 + sub;
    fsh[sub][t] = feature[p*64 + t];
    if (t < 3) fsh[sub][64 + t] = xyz[p*3 + t];
    __syncthreads();
    const float* f = fsh[sub];
    float acc = bv[t];
    #pragma unroll
    for (int c = 0; c < 67; c++)
        acc = fmaf(f[c], Wv[c*64 + t], acc);
    g_vfeat[p*64 + t] = fmaxf(acc, 0.0f);
}

// ---------------------------------------------------------------------------
// Equality-replace insert into a 36-entry register list.
// ---------------------------------------------------------------------------
__device__ __forceinline__ void topk_insert_eq(
    float d, int idx, float* kd, int* ki, float& worst)
{
    #pragma unroll
    for (int s = 0; s < KNNK; s++) {
        bool h = (kd[s] == worst);
        kd[s] = h ? d   : kd[s];
        ki[s] = h ? idx : ki[s];
    }
    float w = kd[0];
    #pragma unroll
    for (int s = 1; s < KNNK; s++)
        w = fmaxf(w, kd[s]);
    worst = w;
}

__device__ __forceinline__ float dist3(const float4& c, float nx, float ny, float nz) {
    float d = fmaf(nx, c.y, c.x);
    d = fmaf(ny, c.z, d);
    return fmaf(nz, c.w, d);
}

// ---------------------------------------------------------------------------
// Threshold kernel: per query, T = 14th smallest distance among the batch's
// first 512 candidates. Sample is smem-resident (8KB, one barrier).
// ---------------------------------------------------------------------------
__global__ __launch_bounds__(KBLK) void knn_thresh_kernel() {
    __shared__ float4 smp[SAMPLE];
    const unsigned FULL = 0xffffffffu;

    int tid = threadIdx.x;
    int q = blockIdx.x * KBLK + tid;
    int b = q >> 13;

    const float4* __restrict__ cand = g_xyz4 + b * NN;
    for (int i = tid; i < SAMPLE; i += KBLK) smp[i] = cand[i];
    __syncthreads();

    float4 me = g_xyz4[q];
    float nx = -2.0f * me.y, ny = -2.0f * me.z, nz = -2.0f * me.w;

    float pd[PKEEP];
    #pragma unroll
    for (int s = 0; s < PKEEP; s++)
        pd[s] = dist3(smp[s], nx, ny, nz);
    float worstA = pd[0];
    #pragma unroll
    for (int s = 1; s < PKEEP; s++) worstA = fmaxf(worstA, pd[s]);

    for (int js = 0; js < SAMPLE; js += 32) {
        unsigned m0 = 0, m1 = 0;
        #pragma unroll
        for (int jj = 0; jj < 16; jj++) {
            float d = dist3(smp[js + jj], nx, ny, nz);
            m0 |= (d < worstA) ? (1u << jj) : 0u;
        }
        #pragma unroll
        for (int jj = 16; jj < 32; jj++) {
            float d = dist3(smp[js + jj], nx, ny, nz);
            m1 |= (d < worstA) ? (1u << jj) : 0u;
        }
        unsigned mask = m0 | m1;
        if (js == 0) mask &= 0xFFFFC000u;  // first 14 already filled

        if (__any_sync(FULL, mask != 0u)) {
            while (mask) {
                int jj = __ffs(mask) - 1;
                mask &= mask - 1;
                float d = dist3(smp[js + jj], nx, ny, nz);
                if (d < worstA) {
                    #pragma unroll
                    for (int s = 0; s < PKEEP; s++) {
                        bool hh = (pd[s] == worstA);
                        pd[s] = hh ? d : pd[s];
                    }
                    float w = pd[0];
                    #pragma unroll
                    for (int s = 1; s < PKEEP; s++) w = fmaxf(w, pd[s]);
                    worstA = w;
                }
            }
        }
    }
    g_T[q] = worstA;
}

// ---------------------------------------------------------------------------
// Collect + per-quarter top-36 (blockIdx.y = quarter). The quarter's 2048
// candidates are smem-resident (32KB, loaded once, no scan-phase barriers).
// Survivors store INDEX ONLY; distances recomputed from the resident tile.
// ---------------------------------------------------------------------------
__global__ __launch_bounds__(KBLK) void knn_select_kernel() {
    __shared__ float4 qt[QPART];           // 32KB quarter tile
    const unsigned FULL = 0xffffffffu;

    int tid = threadIdx.x;
    int q = blockIdx.x * KBLK + tid;
    int h = blockIdx.y;
    int b = q >> 13;

    const float4* __restrict__ cand = g_xyz4 + b * NN + h * QPART;
    for (int i = tid; i < QPART; i += KBLK) qt[i] = cand[i];
    __syncthreads();

    float4 me = g_xyz4[q];
    float nx = -2.0f * me.y, ny = -2.0f * me.z, nz = -2.0f * me.w;
    const float T = g_T[q];
    const int idx_off = h * QPART;

    int si[CAP];
    int cnt = 0;

    for (int js = 0; js < QPART; js += 32) {
        unsigned m0 = 0, m1 = 0, m2 = 0, m3 = 0;
        #pragma unroll
        for (int jj = 0; jj < 8; jj++) {
            float d = dist3(qt[js + jj], nx, ny, nz);
            m0 |= (d <= T) ? (1u << jj) : 0u;
        }
        #pragma unroll
        for (int jj = 8; jj < 16; jj++) {
            float d = dist3(qt[js + jj], nx, ny, nz);
            m1 |= (d <= T) ? (1u << jj) : 0u;
        }
        #pragma unroll
        for (int jj = 16; jj < 24; jj++) {
            float d = dist3(qt[js + jj], nx, ny, nz);
            m2 |= (d <= T) ? (1u << jj) : 0u;
        }
        #pragma unroll
        for (int jj = 24; jj < 32; jj++) {
            float d = dist3(qt[js + jj], nx, ny, nz);
            m3 |= (d <= T) ? (1u << jj) : 0u;
        }
        unsigned mask = (m0 | m1) | (m2 | m3);
        if (__any_sync(FULL, mask != 0u)) {
            while (mask) {
                int jj = __ffs(mask) - 1;
                mask &= mask - 1;
                if (cnt < CAP) si[cnt] = js + jj;
                cnt++;
            }
        }
    }

    g_cnt[(size_t)h * BN + q] = cnt;
    size_t o = ((size_t)h * BN + q) * KNNK;

    if (cnt <= KNNK) {
        for (int s = 0; s < KNNK; s++) {
            bool v = (s < cnt);
            float d = v ? dist3(qt[si[s]], nx, ny, nz) : FINF;
            g_pd[o + s] = d;
            g_pi[o + s] = v ? (idx_off + si[s]) : 0;
        }
    } else if (cnt <= CAP) {
        float kd[KNNK];
        int   ki[KNNK];
        #pragma unroll
        for (int s = 0; s < KNNK; s++) {
            kd[s] = dist3(qt[si[s]], nx, ny, nz);
            ki[s] = idx_off + si[s];
        }
        float worst = kd[0];
        #pragma unroll
        for (int s = 1; s < KNNK; s++) worst = fmaxf(worst, kd[s]);

        for (int it = KNNK; it < cnt; it++) {
            float d = dist3(qt[si[it]], nx, ny, nz);
            if (d < worst)
                topk_insert_eq(d, idx_off + si[it], kd, ki, worst);
        }
        #pragma unroll
        for (int s = 0; s < KNNK; s++) {
            g_pd[o + s] = kd[s];
            g_pi[o + s] = ki[s];
        }
    }
    // cnt > CAP: quarter unusable; fallback (triggered by g_cnt) rewrites.
}

// ---------------------------------------------------------------------------
// Order-preserving float <-> uint maps for bit-bisection selection.
// ---------------------------------------------------------------------------
__device__ __forceinline__ unsigned f2mono(float f) {
    unsigned u = __float_as_uint(f);
    return (u & 0x80000000u) ? ~u : (u | 0x80000000u);
}
__device__ __forceinline__ float mono2f(unsigned m) {
    unsigned u = (m & 0x80000000u) ? (m ^ 0x80000000u) : ~m;
    return __uint_as_float(u);
}

// ---------------------------------------------------------------------------
// Fallback: per-query exactness check (total survivors >= 36 and all quarter
// counts <= CAP); failures (expected ~30/run) get an exact whole-N warp
// bisection. Result overwrites quarter-0 list; quarters 1-3 padded to +INF.
// ---------------------------------------------------------------------------
__global__ __launch_bounds__(KBLK) void knn_fallback_kernel() {
    __shared__ unsigned um[NN];            // 32KB distance cache
    __shared__ int fq[KBLK];
    __shared__ int fn;
    const unsigned FULL = 0xffffffffu;

    int tid = threadIdx.x;
    int q = blockIdx.x * KBLK + tid;

    if (tid == 0) fn = 0;
    __syncthreads();

    int total = 0;
    bool over = false;
    #pragma unroll
    for (int h = 0; h < NSPLIT; h++) {
        int c = g_cnt[(size_t)h * BN + q];
        total += c;
        over |= (c > CAP);
    }
    if (total < KNNK || over) {
        int slot = atomicAdd(&fn, 1);
        fq[slot] = q;
    }
    __syncthreads();

    int nf = fn;
    for (int t = 0; t < nf; t++) {
        int fqq = fq[t];
        int b = fqq >> 13;
        float4 me = g_xyz4[fqq];
        float nx = -2.0f * me.y, ny = -2.0f * me.z, nz = -2.0f * me.w;
        const float4* __restrict__ cand = g_xyz4 + b * NN;

        for (int i = tid; i < NN; i += KBLK) {
            float4 c = cand[i];
            um[i] = f2mono(dist3(c, nx, ny, nz));
        }
        __syncthreads();

        if (tid < 32) {
            int lane = tid;
            unsigned prefix = 0;
            for (int bit = 31; bit >= 0; bit--) {
                unsigned trial = prefix | ((1u << bit) - 1u);
                int cnt = 0;
                for (int i = 0; i < NN/32; i++)
                    cnt += (um[lane + 32*i] <= trial) ? 1 : 0;
                #pragma unroll
                for (int s = 16; s; s >>= 1)
                    cnt += __shfl_xor_sync(FULL, cnt, s);
                if (cnt < KNNK) prefix |= (1u << bit);
            }
            const unsigned V = prefix;

            size_t o = (size_t)fqq * KNNK;
            unsigned lt = (1u << lane) - 1u;
            int base = 0;
            for (int i = 0; i < NN/32 && base < KNNK; i++) {
                int j = lane + 32*i;
                unsigned u = um[j];
                bool hit = (u <= V);
                unsigned m = __ballot_sync(FULL, hit);
                if (hit) {
                    int r = base + __popc(m & lt);
                    if (r < KNNK) {
                        g_pd[o + r] = mono2f(u);
                        g_pi[o + r] = j;
                    }
                }
                base += __popc(m);
            }
            for (int h = 1; h < NSPLIT; h++) {
                size_t oh = ((size_t)h * BN + fqq) * KNNK;
                for (int s = lane; s < KNNK; s += 32) {
                    g_pd[oh + s] = FINF;
                    g_pi[oh + s] = 0;
                }
            }
        }
        __syncthreads();
    }
}

// ---------------------------------------------------------------------------
// Fused 4-way merge + attention + suffix GEMM. Warp per point.
// ---------------------------------------------------------------------------
__global__ __launch_bounds__(256) void attn_kernel(
    const float* __restrict__ feature,
    const float* __restrict__ Wsuf,
    const float* __restrict__ bsuf,
    float* __restrict__ out)
{
    __shared__ int   ish[8][40];
    __shared__ float osh[8][64];
    const unsigned FULL = 0xffffffffu;
    int w    = threadIdx.x >> 5;
    int lane = threadIdx.x & 31;
    int p    = blockIdx.x * 8 + w;
    int b    = p >> 13;

    unsigned uA[NSPLIT], uB[NSPLIT];
    int      iA[NSPLIT], iB[NSPLIT];
    #pragma unroll
    for (int hh = 0; hh < NSPLIT; hh++) {
        size_t oh = ((size_t)hh * BN + p) * KNNK;
        uA[hh] = f2mono(g_pd[oh + lane]);
        iA[hh] = g_pi[oh + lane];
        uB[hh] = 0xFFFFFFFFu; iB[hh] = 0;
        if (lane < 4) {
            uB[hh] = f2mono(g_pd[oh + 32 + lane]);
            iB[hh] = g_pi[oh + 32 + lane];
        }
    }

    unsigned prefix = 0;
    #pragma unroll
    for (int bit = 31; bit >= 0; bit--) {
        unsigned trial = prefix | ((1u << bit) - 1u);
        int cnt = 0;
        #pragma unroll
        for (int hh = 0; hh < NSPLIT; hh++) {
            cnt += __popc(__ballot_sync(FULL, uA[hh] <= trial));
            cnt += __popc(__ballot_sync(FULL, uB[hh] <= trial) & 0xFu);
        }
        if (cnt < KNNK) prefix |= (1u << bit);
    }
    const unsigned V = prefix;

    unsigned lt = (1u << lane) - 1u;
    int base = 0;
    #pragma unroll
    for (int hh = 0; hh < NSPLIT; hh++) {
        unsigned mA = __ballot_sync(FULL, uA[hh] <= V);
        if (uA[hh] <= V) {
            int r = base + __popc(mA & lt);
            if (r < KNNK) ish[w][r] = iA[hh];
        }
        base += __popc(mA);
        unsigned mB = __ballot_sync(FULL, uB[hh] <= V) & 0xFu;
        if (lane < 4 && (uB[hh] <= V)) {
            int r = base + __popc(mB & lt);
            if (r < KNNK) ish[w][r] = iB[hh];
        }
        base += __popc(mB);
    }
    __syncwarp();

    int idxA = ish[w][lane];
    int idxB = (lane < 4) ? ish[w][32 + lane] : 0;

    const float* frow = feature + (size_t)p * 64;
    float2 q2 = *(const float2*)(frow + 2*lane);

    const float* fbase = feature + (size_t)b * NN * 64;
    float wA = 0.0f, wB = -3.4e38f;

    #pragma unroll
    for (int k = 0; k < KNNK; k++) {
        int j = (k < 32) ? __shfl_sync(FULL, idxA, k)
                         : __shfl_sync(FULL, idxB, k - 32);
        float2 f2 = *(const float2*)(fbase + (size_t)j * 64 + 2*lane);
        float part = fmaf(f2.x, q2.x, f2.y * q2.y);
        #pragma unroll
        for (int s = 16; s; s >>= 1)
            part += __shfl_xor_sync(FULL, part, s);
        if (k < 32) { if (lane == k)      wA = part; }
        else        { if (lane == k - 32) wB = part; }
    }

    float m = fmaxf(wA, (lane < 4) ? wB : -3.4e38f);
    #pragma unroll
    for (int s = 16; s; s >>= 1)
        m = fmaxf(m, __shfl_xor_sync(FULL, m, s));
    float eA = __expf(wA - m);
    float eB = (lane < 4) ? __expf(wB - m) : 0.0f;
    float ssum = eA + eB;
    #pragma unroll
    for (int s = 16; s; s >>= 1)
        ssum += __shfl_xor_sync(FULL, ssum, s);
    float inv = 1.0f / ssum;
    eA *= inv; eB *= inv;

    const float* vbase = g_vfeat + (size_t)b * NN * 64;
    float ox = 0.0f, oy = 0.0f;
    #pragma unroll
    for (int k = 0; k < KNNK; k++) {
        int j; float wk;
        if (k < 32) { j = __shfl_sync(FULL, idxA, k);      wk = __shfl_sync(FULL, eA, k); }
        else        { j = __shfl_sync(FULL, idxB, k - 32); wk = __shfl_sync(FULL, eB, k - 32); }
        float2 v2 = *(const float2*)(vbase + (size_t)j * 64 + 2*lane);
        ox = fmaf(wk, v2.x, ox);
        oy = fmaf(wk, v2.y, oy);
    }

    osh[w][2*lane]     = ox;
    osh[w][2*lane + 1] = oy;
    __syncwarp();
    float2 acc = *(const float2*)(bsuf + 2*lane);
    #pragma unroll 8
    for (int c = 0; c < 64; c++) {
        float oc = osh[w][c];
        float2 wv = *(const float2*)(Wsuf + c*64 + 2*lane);
        acc.x = fmaf(oc, wv.x, acc.x);
        acc.y = fmaf(oc, wv.y, acc.y);
    }
    *(float2*)(out + (size_t)p * 64 + 2*lane) = acc;
}

__global__ void tail_kernel(float* __restrict__ out, int out_size) {
    int i = BN*OUTD + blockIdx.x * blockDim.x + threadIdx.x;
    if (i < out_size) out[i] = (float)NN;
}

extern "C" void kernel_launch(void* const* d_in, const int* in_sizes, int n_in,
                              void* d_out, int out_size) {
    const float* feature = (const float*)d_in[0];
    const float* xyz     = (const float*)d_in[1];
    const float* Wv      = (const float*)d_in[2];
    const float* bv      = (const float*)d_in[3];
    const float* Wsuf    = (const float*)d_in[4];
    const float* bsuf    = (const float*)d_in[5];
    float* out = (float*)d_out;

    pack_xyz_kernel<<<(BN + 255) / 256, 256>>>(xyz);
    vfeat_kernel<<<BN / 4, 256>>>(feature, xyz, Wv, bv);
    knn_thresh_kernel<<<BN / KBLK, KBLK>>>();
    dim3 kgrid(BN / KBLK, NSPLIT);
    knn_select_kernel<<<kgrid, KBLK>>>();
    knn_fallback_kernel<<<BN / KBLK, KBLK>>>();
    attn_kernel<<<BN / 8, 256>>>(feature, Wsuf, bsuf, out);

    if (out_size > BN*OUTD) {
        int extra = out_size - BN*OUTD;
        tail_kernel<<<(extra + 255) / 256, 256>>>(out, out_size);
    }
}